// round 2
// baseline (speedup 1.0000x reference)
#include <cuda_runtime.h>

#define BB 2
#define CC 64
#define NN (64*64*64)          // 262144 tokens per batch
#define NHEADS 4
#define DH 32
#define HID 128
#define EPSL 1e-5f
#define PBG 512                // gram partial blocks per batch
#define TOKB (NN/PBG)          // 512 tokens per gram block

// ---- scratch (device globals; no allocation) ----
__device__ float g_part[BB*PBG*CC*CC];   // 16 MB gram partials
__device__ float g_G[BB*CC*CC];          // gram matrices
__device__ float g_M[BB*HID*CC];         // per-head fold M [b][128][64]
__device__ float g_Pp[BB*CC*CC];         // P' stored k-major: [b][c][o]
__device__ float g_bp[BB*CC];            // b'

// ============================================================
// Kernel 1: partial Gram  G[b] += X_chunk X_chunkT
// block: 256 threads, 512 tokens, tiles of 128 tokens in smem
// thread (tr,tc) computes 4x4 tile at rows {tr+16i}, cols {tc+16j}
// ============================================================
__global__ void __launch_bounds__(256, 2)
gram_kernel(const float* __restrict__ x) {
    const int b  = blockIdx.y;
    const int pb = blockIdx.x;
    const float* xb = x + (size_t)b * CC * NN + (size_t)pb * TOKB;

    __shared__ float xs[CC * 132];   // [c][t], row stride 132 (33*16B -> float4 aligned)

    const int tid = threadIdx.x;
    const int tr = tid & 15;
    const int tc = tid >> 4;

    float acc[4][4];
#pragma unroll
    for (int i = 0; i < 4; i++)
#pragma unroll
        for (int j = 0; j < 4; j++) acc[i][j] = 0.0f;

    for (int tile = 0; tile < TOKB; tile += 128) {
        __syncthreads();
        // load 64 channels x 128 tokens (coalesced float4 along tokens)
#pragma unroll
        for (int l = 0; l < 8; l++) {
            int idx = l * 256 + tid;         // 2048 float4s
            int c  = idx >> 5;
            int t4 = (idx & 31) * 4;
            float4 v = *(const float4*)(xb + (size_t)c * NN + tile + t4);
            *(float4*)&xs[c * 132 + t4] = v;
        }
        __syncthreads();

#pragma unroll 2
        for (int t = 0; t < 128; t += 4) {
            float4 av[4], bv[4];
#pragma unroll
            for (int i = 0; i < 4; i++) av[i] = *(float4*)&xs[(tr + 16 * i) * 132 + t];
#pragma unroll
            for (int j = 0; j < 4; j++) bv[j] = *(float4*)&xs[(tc + 16 * j) * 132 + t];
#pragma unroll
            for (int i = 0; i < 4; i++)
#pragma unroll
                for (int j = 0; j < 4; j++) {
                    acc[i][j] += av[i].x * bv[j].x;
                    acc[i][j] += av[i].y * bv[j].y;
                    acc[i][j] += av[i].z * bv[j].z;
                    acc[i][j] += av[i].w * bv[j].w;
                }
        }
    }

    float* gp = g_part + (size_t)(b * PBG + pb) * CC * CC;
#pragma unroll
    for (int i = 0; i < 4; i++)
#pragma unroll
        for (int j = 0; j < 4; j++)
            gp[(tr + 16 * i) * CC + (tc + 16 * j)] = acc[i][j];
}

// ============================================================
// Kernel 2: reduce 512 partials -> G
// grid (64, BB), 256 threads; 64 elements/block, 4 threads/element
// ============================================================
__global__ void __launch_bounds__(256)
gram_reduce() {
    const int b   = blockIdx.y;
    const int tid = threadIdx.x;
    const int el  = tid & 63;
    const int pq  = tid >> 6;      // 0..3
    const int e   = blockIdx.x * 64 + el;

    const float* base = g_part + (size_t)b * PBG * CC * CC + e;
    float s0 = 0.f, s1 = 0.f, s2 = 0.f, s3 = 0.f;
    for (int p = pq * 4; p < PBG; p += 16) {
        s0 += base[(size_t)(p + 0) * 4096];
        s1 += base[(size_t)(p + 1) * 4096];
        s2 += base[(size_t)(p + 2) * 4096];
        s3 += base[(size_t)(p + 3) * 4096];
    }
    __shared__ float red[256];
    red[tid] = s0 + s1 + s2 + s3;
    __syncthreads();
    if (pq == 0)
        g_G[b * 4096 + e] = red[el] + red[64 + el] + red[128 + el] + red[192 + el];
}

// ============================================================
// Kernel 3: per (head, batch):  M_h = scale * (Wk_h G Wv_h^T / 4096)^T Wq_h
// ============================================================
__global__ void __launch_bounds__(128)
computeM(const float* __restrict__ wqkv) {
    const int h = blockIdx.x, b = blockIdx.y, tid = threadIdx.x; // 128 threads
    __shared__ float Gs[4096];   // 16 KB
    __shared__ float GV[2048];   //  8 KB  [r][e]
    __shared__ float Cs[1024];   //  4 KB  [d][e]

    for (int i = tid; i < 4096; i += 128) Gs[i] = g_G[b * 4096 + i];
    __syncthreads();

    // GV[r][e] = sum_c G[r][c] * Wv[h*32+e][c]
    for (int i = tid; i < 2048; i += 128) {
        int r = i >> 5, e = i & 31;
        const float* wvr = wqkv + (256 + h * 32 + e) * 64;
        float s = 0.f;
#pragma unroll
        for (int c = 0; c < 64; c++) s += Gs[r * 64 + c] * __ldg(&wvr[c]);
        GV[i] = s;
    }
    __syncthreads();

    // C[d][e] = (sum_r Wk[h*32+d][r] * GV[r][e]) / (H*W=4096)
    for (int i = tid; i < 1024; i += 128) {
        int d = i >> 5, e = i & 31;
        const float* wkr = wqkv + (128 + h * 32 + d) * 64;
        float s = 0.f;
#pragma unroll
        for (int r = 0; r < 64; r++) s += __ldg(&wkr[r]) * GV[r * 32 + e];
        Cs[i] = s * (1.0f / 4096.0f);
    }
    __syncthreads();

    // M[e][c] = scale * sum_d C[d][e] * Wq[h*32+d][c]
    const float scale = 0.17677669529663687f;  // 32^-0.5
    for (int i = tid; i < 2048; i += 128) {
        int e = i >> 6, c = i & 63;
        float s = 0.f;
#pragma unroll
        for (int d = 0; d < 32; d++) s += Cs[d * 32 + e] * __ldg(&wqkv[(h * 32 + d) * 64 + c]);
        g_M[b * HID * 64 + (h * 32 + e) * 64 + c] = scale * s;
    }
}

// ============================================================
// Kernel 4: P = w_out @ M, fold LN-mean:  P' = P - colmean(P), b' = b - mean(b)
// stores P' transposed (k-major) for the apply kernel
// ============================================================
__global__ void __launch_bounds__(256)
computeP(const float* __restrict__ wout, const float* __restrict__ bout) {
    const int b = blockIdx.x, tid = threadIdx.x;  // 256 threads
    __shared__ float Ms[HID * 64];  // 32 KB (reused for mu afterwards)
    __shared__ float Ps[4096];      // 16 KB

    for (int i = tid; i < HID * 64; i += 256) Ms[i] = g_M[b * HID * 64 + i];
    __syncthreads();

    for (int i = tid; i < 4096; i += 256) {
        int o = i >> 6, c = i & 63;
        float s = 0.f;
#pragma unroll 8
        for (int m = 0; m < 128; m++) s += __ldg(&wout[o * 128 + m]) * Ms[m * 64 + c];
        Ps[i] = s;
    }
    __syncthreads();

    float* mu = Ms;  // Ms is dead now; reuse for column means + bias mean
    if (tid < 64) {
        float s = 0.f;
#pragma unroll
        for (int o = 0; o < 64; o++) s += Ps[o * 64 + tid];
        mu[tid] = s * (1.0f / 64.0f);
    }
    if (tid == 64) {
        float s = 0.f;
        for (int o = 0; o < 64; o++) s += __ldg(&bout[o]);
        mu[64] = s * (1.0f / 64.0f);
    }
    __syncthreads();

    for (int i = tid; i < 4096; i += 256) {
        int c = i >> 6, o = i & 63;
        g_Pp[b * 4096 + i] = Ps[o * 64 + c] - mu[c];   // transposed store [c][o]
    }
    if (tid < 64) g_bp[b * 64 + tid] = __ldg(&bout[tid]) - mu[64];
}

// ============================================================
// Kernel 5: apply  y' = P' x + b'; out = y' * rsqrt(mean(y'^2)+eps) * g
// block: 64 channels x 128 tokens; thread tile 8 rows x 4 tokens
// ============================================================
__global__ void __launch_bounds__(256, 2)
apply_kernel(const float* __restrict__ x,
             const float* __restrict__ gg,
             float* __restrict__ out) {
    const int b  = blockIdx.y;
    const int n0 = blockIdx.x * 128;

    __shared__ float xs[CC * 128];  // 32 KB, [c][t]
    __shared__ float pk[CC * 64];   // 16 KB, [k][o]; reused for ssq/rs in epilogue

    const int tid = threadIdx.x;
    const float* xb = x + (size_t)b * CC * NN + n0;

#pragma unroll
    for (int l = 0; l < 8; l++) {
        int idx = l * 256 + tid;         // 2048 float4s
        int c  = idx >> 5;
        int t4 = (idx & 31) * 4;
        *(float4*)&xs[c * 128 + t4] = *(const float4*)(xb + (size_t)c * NN + t4);
    }
#pragma unroll
    for (int l = 0; l < 4; l++) {
        int idx = l * 256 + tid;         // 1024 float4s = 4096 floats
        *(float4*)&pk[idx * 4] = *(const float4*)(g_Pp + b * 4096 + idx * 4);
    }
    __syncthreads();

    const int tr = tid >> 5;            // 0..7
    const int t0 = (tid & 31) * 4;      // token offset
    const int r0 = tr * 8;              // row offset

    float acc[8][4];
#pragma unroll
    for (int i = 0; i < 8; i++)
#pragma unroll
        for (int j = 0; j < 4; j++) acc[i][j] = 0.0f;

#pragma unroll 4
    for (int k = 0; k < 64; k++) {
        float4 a0 = *(float4*)&pk[k * 64 + r0];
        float4 a1 = *(float4*)&pk[k * 64 + r0 + 4];
        float4 bv = *(float4*)&xs[k * 128 + t0];
        float a[8] = {a0.x, a0.y, a0.z, a0.w, a1.x, a1.y, a1.z, a1.w};
        float bj[4] = {bv.x, bv.y, bv.z, bv.w};
#pragma unroll
        for (int i = 0; i < 8; i++)
#pragma unroll
            for (int j = 0; j < 4; j++) acc[i][j] += a[i] * bj[j];
    }
    __syncthreads();   // pk now dead -> reuse

    float* ssq_s = pk;            // [8][128]
    float* rs_s  = pk + 1024;     // [128]

    float ssq[4] = {0.f, 0.f, 0.f, 0.f};
#pragma unroll
    for (int i = 0; i < 8; i++) {
        float bpv = __ldg(&g_bp[b * 64 + r0 + i]);
#pragma unroll
        for (int j = 0; j < 4; j++) {
            float v = acc[i][j] + bpv;
            acc[i][j] = v;
            ssq[j] += v * v;
        }
    }
#pragma unroll
    for (int j = 0; j < 4; j++) ssq_s[tr * 128 + t0 + j] = ssq[j];
    __syncthreads();

    if (tid < 128) {
        float s = 0.f;
#pragma unroll
        for (int r = 0; r < 8; r++) s += ssq_s[r * 128 + tid];
        rs_s[tid] = rsqrtf(s * (1.0f / 64.0f) + EPSL);
    }
    __syncthreads();

    float rsv[4];
#pragma unroll
    for (int j = 0; j < 4; j++) rsv[j] = rs_s[t0 + j];

    float* ob = out + (size_t)b * CC * NN + n0;
#pragma unroll
    for (int i = 0; i < 8; i++) {
        float gv = __ldg(&gg[r0 + i]);
        float4 o4;
        o4.x = acc[i][0] * rsv[0] * gv;
        o4.y = acc[i][1] * rsv[1] * gv;
        o4.z = acc[i][2] * rsv[2] * gv;
        o4.w = acc[i][3] * rsv[3] * gv;
        *(float4*)(ob + (size_t)(r0 + i) * NN + t0) = o4;
    }
}

// ============================================================
extern "C" void kernel_launch(void* const* d_in, const int* in_sizes, int n_in,
                              void* d_out, int out_size) {
    const float* x    = (const float*)d_in[0];
    const float* wqkv = (const float*)d_in[1];
    const float* wout = (const float*)d_in[2];
    const float* bout = (const float*)d_in[3];
    const float* g    = (const float*)d_in[4];
    float* out = (float*)d_out;

    gram_kernel<<<dim3(PBG, BB), 256>>>(x);
    gram_reduce<<<dim3(64, BB), 256>>>();
    computeM<<<dim3(NHEADS, BB), 128>>>(wqkv);
    computeP<<<BB, 256>>>(wout, bout);
    apply_kernel<<<dim3(NN / 128, BB), 256>>>(x, g, out);
}

// round 4
// speedup vs baseline: 1.2184x; 1.2184x over previous
#include <cuda_runtime.h>

#define BB 2
#define CC 64
#define NN (64*64*64)          // 262144 tokens per batch
#define NHEADS 4
#define HID 128
#define EPSL 1e-5f
#define PBG 512                // gram partial blocks per batch
#define TOKB (NN/PBG)          // 512 tokens per gram block

typedef unsigned long long u64;

// ---- scratch (device globals; no allocation) ----
__device__ float g_part[BB*PBG*CC*CC];   // 16 MB gram partials
__device__ float g_G[BB*CC*CC];          // gram matrices
__device__ float g_M[BB*HID*CC];         // per-head fold M [b][128][64]
__device__ float g_Pp[BB*CC*CC];         // P' stored k-major: [b][c][o]
__device__ float g_bp[BB*CC];            // b'

// ---- packed fp32x2 helpers (ptxas never auto-fuses; PTX-only; sm_100+) ----
__device__ __forceinline__ void ffma2(u64& d, u64 a, u64 b) {
    asm("fma.rn.f32x2 %0, %1, %2, %0;" : "+l"(d) : "l"(a), "l"(b));
}
__device__ __forceinline__ u64 pack2(float a, float b) {
    u64 r; asm("mov.b64 %0, {%1, %2};" : "=l"(r) : "f"(a), "f"(b)); return r;
}
__device__ __forceinline__ float2 unpack2(u64 v) {
    float2 r; asm("mov.b64 {%0, %1}, %2;" : "=f"(r.x), "=f"(r.y) : "l"(v)); return r;
}

// ============================================================
// Kernel 1: partial Gram  G[b] += X_chunk X_chunkT   (f32x2 packed)
// block: 256 threads, 512 tokens, tiles of 128 tokens in smem
// ============================================================
__global__ void __launch_bounds__(256, 2)
gram_kernel(const float* __restrict__ x) {
    const int b  = blockIdx.y;
    const int pb = blockIdx.x;
    const float* xb = x + (size_t)b * CC * NN + (size_t)pb * TOKB;

    __shared__ float xs[CC * 132];   // [c][t], row stride 132 floats (16B-aligned rows)

    const int tid = threadIdx.x;
    const int tr = tid & 15;
    const int tc = tid >> 4;

    u64 acc2[4][4];                  // packed pair accumulators (lo,hi over token dim)
#pragma unroll
    for (int i = 0; i < 4; i++)
#pragma unroll
        for (int j = 0; j < 4; j++) acc2[i][j] = 0ull;

    for (int tile = 0; tile < TOKB; tile += 128) {
        __syncthreads();
#pragma unroll
        for (int l = 0; l < 8; l++) {
            int idx = l * 256 + tid;         // 2048 float4s
            int c  = idx >> 5;
            int t4 = (idx & 31) * 4;
            float4 v = *(const float4*)(xb + (size_t)c * NN + tile + t4);
            *(float4*)&xs[c * 132 + t4] = v;
        }
        __syncthreads();

#pragma unroll 2
        for (int t = 0; t < 128; t += 4) {
            ulonglong2 av[4], bv[4];   // .x = (x[t],x[t+1]) packed, .y = (x[t+2],x[t+3])
#pragma unroll
            for (int i = 0; i < 4; i++) av[i] = *(const ulonglong2*)&xs[(tr + 16 * i) * 132 + t];
#pragma unroll
            for (int j = 0; j < 4; j++) bv[j] = *(const ulonglong2*)&xs[(tc + 16 * j) * 132 + t];
#pragma unroll
            for (int i = 0; i < 4; i++)
#pragma unroll
                for (int j = 0; j < 4; j++) {
                    ffma2(acc2[i][j], av[i].x, bv[j].x);
                    ffma2(acc2[i][j], av[i].y, bv[j].y);
                }
        }
    }

    float* gp = g_part + (size_t)(b * PBG + pb) * CC * CC;
#pragma unroll
    for (int i = 0; i < 4; i++)
#pragma unroll
        for (int j = 0; j < 4; j++) {
            float2 p = unpack2(acc2[i][j]);
            gp[(tr + 16 * i) * CC + (tc + 16 * j)] = p.x + p.y;
        }
}

// ============================================================
// Kernel 2: reduce 512 partials -> G
// ============================================================
__global__ void __launch_bounds__(256)
gram_reduce() {
    const int b   = blockIdx.y;
    const int tid = threadIdx.x;
    const int el  = tid & 63;
    const int pq  = tid >> 6;
    const int e   = blockIdx.x * 64 + el;

    const float* base = g_part + (size_t)b * PBG * CC * CC + e;
    float s0 = 0.f, s1 = 0.f, s2 = 0.f, s3 = 0.f;
    for (int p = pq * 4; p < PBG; p += 16) {
        s0 += base[(size_t)(p + 0) * 4096];
        s1 += base[(size_t)(p + 1) * 4096];
        s2 += base[(size_t)(p + 2) * 4096];
        s3 += base[(size_t)(p + 3) * 4096];
    }
    __shared__ float red[256];
    red[tid] = s0 + s1 + s2 + s3;
    __syncthreads();
    if (pq == 0)
        g_G[b * 4096 + e] = red[el] + red[64 + el] + red[128 + el] + red[192 + el];
}

// ============================================================
// Kernel 3: per (head, batch):  M_h = scale * (Wk_h G Wv_h^T / 4096)^T Wq_h
// all operands staged through smem (no LDG in inner loops)
// ============================================================
__global__ void __launch_bounds__(256)
computeM(const float* __restrict__ wqkv) {
    const int h = blockIdx.x, b = blockIdx.y, tid = threadIdx.x; // 256 threads
    __shared__ float Gs[4096];   // 16 KB
    __shared__ float GV[2048];   //  8 KB  [r][e]
    __shared__ float Ws[2048];   //  8 KB  reused: Wv -> Wk -> Wq
    __shared__ float Cs[1024];   //  4 KB  [d][e]

    // stage G and Wv
    for (int i = tid; i < 4096; i += 256) Gs[i] = g_G[b * 4096 + i];
    for (int i = tid; i < 2048; i += 256) Ws[i] = wqkv[(256 + h * 32) * 64 + i]; // Wv_h [e][c]
    __syncthreads();

    // GV[r][e] = sum_c G[r][c] * Wv[e][c]
    for (int i = tid; i < 2048; i += 256) {
        int r = i >> 5, e = i & 31;
        float s = 0.f;
#pragma unroll
        for (int c = 0; c < 64; c++) s += Gs[r * 64 + c] * Ws[e * 64 + c];
        GV[i] = s;
    }
    __syncthreads();

    // stage Wk (Ws reused)
    for (int i = tid; i < 2048; i += 256) Ws[i] = wqkv[(128 + h * 32) * 64 + i]; // Wk_h [d][r]
    __syncthreads();

    // C[d][e] = (sum_r Wk[d][r] * GV[r][e]) / 4096
    for (int i = tid; i < 1024; i += 256) {
        int d = i >> 5, e = i & 31;
        float s = 0.f;
#pragma unroll
        for (int r = 0; r < 64; r++) s += Ws[d * 64 + r] * GV[r * 32 + e];
        Cs[i] = s * (1.0f / 4096.0f);
    }
    __syncthreads();

    // stage Wq
    for (int i = tid; i < 2048; i += 256) Ws[i] = wqkv[(h * 32) * 64 + i]; // Wq_h [d][c]
    __syncthreads();

    // M[e][c] = scale * sum_d C[d][e] * Wq[d][c]
    const float scale = 0.17677669529663687f;  // 32^-0.5
    for (int i = tid; i < 2048; i += 256) {
        int e = i >> 6, c = i & 63;
        float s = 0.f;
#pragma unroll
        for (int d = 0; d < 32; d++) s += Cs[d * 32 + e] * Ws[d * 64 + c];
        g_M[b * HID * 64 + (h * 32 + e) * 64 + c] = scale * s;
    }
}

// ============================================================
// Kernel 4: P = w_out @ M, fold LN-mean via colmean(P) = colmean(w_out) @ M
// grid (4, BB): each block owns 16 output rows; fully parallel
// stores P' transposed (k-major: [c][o])
// ============================================================
__global__ void __launch_bounds__(256)
computeP(const float* __restrict__ wout, const float* __restrict__ bout) {
    const int b  = blockIdx.y;
    const int o0 = blockIdx.x * 16;
    const int tid = threadIdx.x;

    __shared__ float Ms[HID * 64];   // 32 KB
    __shared__ float Wo[16 * HID];   //  8 KB (row slice of w_out)
    __shared__ float wbar[HID];
    __shared__ float colmu[64];

    for (int i = tid; i < HID * 64; i += 256)
        Ms[i] = g_M[b * HID * 64 + i];
    for (int i = tid; i < 16 * HID; i += 256)
        Wo[i] = wout[o0 * HID + i];
    if (tid < HID) {                       // wbar[m] = mean_o wout[o][m]
        float s = 0.f;
#pragma unroll
        for (int o = 0; o < 64; o++) s += __ldg(&wout[o * HID + tid]);
        wbar[tid] = s * (1.0f / 64.0f);
    }
    __syncthreads();

    if (tid < 64) {                        // colmu[c] = wbar @ M[:,c]
        float s = 0.f;
#pragma unroll 8
        for (int m = 0; m < HID; m++) s += wbar[m] * Ms[m * 64 + tid];
        colmu[tid] = s;
    }
    __syncthreads();

    // P'[o][c] = wout[o,:]@M[:,c] - colmu[c], stored transposed [c][o]
    for (int i = tid; i < 1024; i += 256) {
        int ol = i >> 6, c = i & 63;
        float s = 0.f;
#pragma unroll 8
        for (int m = 0; m < HID; m++) s += Wo[ol * HID + m] * Ms[m * 64 + c];
        g_Pp[b * 4096 + c * 64 + (o0 + ol)] = s - colmu[c];
    }

    if (blockIdx.x == 0 && tid < 64) {     // b' = bout - mean(bout)
        float s = 0.f;
        for (int o = 0; o < 64; o++) s += __ldg(&bout[o]);
        g_bp[b * 64 + tid] = __ldg(&bout[tid]) - s * (1.0f / 64.0f);
    }
}

// ============================================================
// Kernel 5: apply  y' = P' x + b'; out = y' * rsqrt(mean(y'^2)+eps) * g
// f32x2 packed over the row (output-channel) dimension
// ============================================================
__global__ void __launch_bounds__(256, 2)
apply_kernel(const float* __restrict__ x,
             const float* __restrict__ gg,
             float* __restrict__ out) {
    const int b  = blockIdx.y;
    const int n0 = blockIdx.x * 128;

    __shared__ float xs[CC * 128];  // 32 KB, [c][t]
    __shared__ float pk[CC * 64];   // 16 KB, [k][o]; reused for ssq/rs in epilogue

    const int tid = threadIdx.x;
    const float* xb = x + (size_t)b * CC * NN + n0;

#pragma unroll
    for (int l = 0; l < 8; l++) {
        int idx = l * 256 + tid;
        int c  = idx >> 5;
        int t4 = (idx & 31) * 4;
        *(float4*)&xs[c * 128 + t4] = *(const float4*)(xb + (size_t)c * NN + t4);
    }
#pragma unroll
    for (int l = 0; l < 4; l++) {
        int idx = l * 256 + tid;
        *(float4*)&pk[idx * 4] = *(const float4*)(g_Pp + b * 4096 + idx * 4);
    }
    __syncthreads();

    const int tr = tid >> 5;            // 0..7
    const int t0 = (tid & 31) * 4;      // token offset
    const int r0 = tr * 8;              // row offset

    u64 acc2[4][4];                     // rows packed in pairs: (r0+2i2, r0+2i2+1) x 4 tokens
#pragma unroll
    for (int i = 0; i < 4; i++)
#pragma unroll
        for (int j = 0; j < 4; j++) acc2[i][j] = 0ull;

#pragma unroll 4
    for (int k = 0; k < 64; k++) {
        ulonglong2 a01 = *(const ulonglong2*)&pk[k * 64 + r0];      // (r0,r0+1),(r0+2,r0+3)
        ulonglong2 a23 = *(const ulonglong2*)&pk[k * 64 + r0 + 4];  // (r0+4,..),(r0+6,..)
        float4 bv = *(const float4*)&xs[k * 128 + t0];
        u64 a2[4] = {a01.x, a01.y, a23.x, a23.y};
        u64 b2[4] = {pack2(bv.x, bv.x), pack2(bv.y, bv.y),
                     pack2(bv.z, bv.z), pack2(bv.w, bv.w)};
#pragma unroll
        for (int i2 = 0; i2 < 4; i2++)
#pragma unroll
            for (int j = 0; j < 4; j++) ffma2(acc2[i2][j], a2[i2], b2[j]);
    }
    __syncthreads();   // pk now dead -> reuse

    // unpack
    float acc[8][4];
#pragma unroll
    for (int i2 = 0; i2 < 4; i2++)
#pragma unroll
        for (int j = 0; j < 4; j++) {
            float2 p = unpack2(acc2[i2][j]);
            acc[2 * i2][j] = p.x;
            acc[2 * i2 + 1][j] = p.y;
        }

    float* ssq_s = pk;            // [8][128]
    float* rs_s  = pk + 1024;     // [128]

    float ssq[4] = {0.f, 0.f, 0.f, 0.f};
#pragma unroll
    for (int i = 0; i < 8; i++) {
        float bpv = __ldg(&g_bp[b * 64 + r0 + i]);
#pragma unroll
        for (int j = 0; j < 4; j++) {
            float v = acc[i][j] + bpv;
            acc[i][j] = v;
            ssq[j] += v * v;
        }
    }
#pragma unroll
    for (int j = 0; j < 4; j++) ssq_s[tr * 128 + t0 + j] = ssq[j];
    __syncthreads();

    if (tid < 128) {
        float s = 0.f;
#pragma unroll
        for (int r = 0; r < 8; r++) s += ssq_s[r * 128 + tid];
        rs_s[tid] = rsqrtf(s * (1.0f / 64.0f) + EPSL);
    }
    __syncthreads();

    float rsv[4];
#pragma unroll
    for (int j = 0; j < 4; j++) rsv[j] = rs_s[t0 + j];

    float* ob = out + (size_t)b * CC * NN + n0;
#pragma unroll
    for (int i = 0; i < 8; i++) {
        float gv = __ldg(&gg[r0 + i]);
        float4 o4;
        o4.x = acc[i][0] * rsv[0] * gv;
        o4.y = acc[i][1] * rsv[1] * gv;
        o4.z = acc[i][2] * rsv[2] * gv;
        o4.w = acc[i][3] * rsv[3] * gv;
        *(float4*)(ob + (size_t)(r0 + i) * NN + t0) = o4;
    }
}

// ============================================================
extern "C" void kernel_launch(void* const* d_in, const int* in_sizes, int n_in,
                              void* d_out, int out_size) {
    const float* x    = (const float*)d_in[0];
    const float* wqkv = (const float*)d_in[1];
    const float* wout = (const float*)d_in[2];
    const float* bout = (const float*)d_in[3];
    const float* g    = (const float*)d_in[4];
    float* out = (float*)d_out;

    gram_kernel<<<dim3(PBG, BB), 256>>>(x);
    gram_reduce<<<dim3(64, BB), 256>>>();
    computeM<<<dim3(NHEADS, BB), 256>>>(wqkv);
    computeP<<<dim3(4, BB), 256>>>(wout, bout);
    apply_kernel<<<dim3(NN / 128, BB), 256>>>(x, g, out);
}